// round 15
// baseline (speedup 1.0000x reference)
#include <cuda_runtime.h>
#include <cuda_fp16.h>
#include <mma.h>
#include <math.h>
#include <cstdint>

using namespace nvcuda;

#define NB 4
#define NH 16
#define SL 1024
#define DH 64
#define ED 1024
#define MTOT (NB*SL)          // 4096
#define BHN (NB*NH)           // 64

// ---- fp16 hi/lo split scratch (allocation-free) ----
__device__ __half s_q [2][(size_t)MTOT*ED];
__device__ __half s_k [2][(size_t)MTOT*ED];
__device__ __half s_v [2][(size_t)MTOT*ED];
__device__ __half s_Wq[2][(size_t)ED*ED];
__device__ __half s_Wk[2][(size_t)ED*ED];
__device__ __half s_Wv[2][(size_t)ED*ED];
__device__ __half s_Wo[2][(size_t)ED*ED];
__device__ __half s_Q [2][(size_t)BHN*SL*DH];   // [bh][l][d]
__device__ __half s_K [2][(size_t)BHN*SL*DH];   // [bh][l][d]
__device__ __half s_Vt[2][(size_t)BHN*DH*SL];   // [bh][d][l]
__device__ __half s_O [2][(size_t)2*MTOT*ED];   // pos|neg [B,L,E]

#define STAGE_BYTES 40960
#define AHI_OFF 0
#define ALO_OFF 10240
#define BHI_OFF 20480
#define BLO_OFF 30720
#define SMEM_BYTES 81920
#define LDSH 40                // smem fp16 row stride (halves)
#define LDC 136                // smem fp32 epilogue stride

__device__ __forceinline__ uint32_t s2u(const void* p){
    uint32_t a; asm("{ .reg .u64 t; cvta.to.shared.u64 t, %1; cvt.u32.u64 %0, t; }":"=r"(a):"l"(p)); return a;
}
#define CPA(dst, src) asm volatile("cp.async.cg.shared.global [%0], [%1], 16;" :: "r"(dst), "l"(src))
#define CPC()  asm volatile("cp.async.commit_group;")
#define CPW0() asm volatile("cp.async.wait_group 0;")
#define CPW1() asm volatile("cp.async.wait_group 1;")

__device__ __forceinline__ void split1(float x, __half& h, __half& l){
    h = __float2half_rn(x);
    l = __float2half_rn(x - __half2float(h));
}

typedef wmma::fragment<wmma::matrix_a, 16,16,16, __half, wmma::row_major> FA;
typedef wmma::fragment<wmma::matrix_b, 16,16,16, __half, wmma::col_major> FB;
typedef wmma::fragment<wmma::accumulator, 16,16,16, float> FC;

// ============================================================
// MODE 0: C=A@W^T+bias -> fp16 hi/lo scatter [bh][l][d]   (Q/K proj)
// MODE 1: C=A@W^T+bias -> fp16 hi/lo scatter [bh][d][l]   (V proj -> Vt)
// MODE 2: C=A@W^T+bias -> fp32 [m][n]                     (out proj)
// MODE 3: S = Q@K^T * 0.125 -> fp32  (per-head, Kdim=64)
// ============================================================
template<int MODE>
__global__ __launch_bounds__(256)
void gemm_f16(const __half* __restrict__ Agh, const __half* __restrict__ Agl,
              const __half* __restrict__ Bgh, const __half* __restrict__ Bgl,
              const float* __restrict__ bias,
              float* __restrict__ Cf, __half* __restrict__ Chi, __half* __restrict__ Clo)
{
    constexpr int NK   = (MODE==3) ? 2  : 32;
    constexpr int LDAg = (MODE==3) ? 64 : 1024;
    constexpr int LDBg = (MODE==3) ? 64 : 1024;
    constexpr int TM   = 64;
    constexpr int MF   = 4;
    constexpr int NF   = 2;

    extern __shared__ char smem[];
    const uint32_t sb = s2u(smem);
    const int t = threadIdx.x;
    const int wid = t >> 5;
    const int wr = wid & 1, wc = wid >> 1;

    const int m0 = blockIdx.y * 128;
    const int n0 = blockIdx.x * 128;
    const int bz = blockIdx.z;

    if (MODE==3) {
        size_t ab = ((size_t)bz*SL + m0) * 64, bb = ((size_t)bz*SL + n0) * 64;
        Agh += ab; Agl += ab; Bgh += bb; Bgl += bb;
    } else {
        Agh += (size_t)m0*1024; Agl += (size_t)m0*1024;
        Bgh += (size_t)n0*1024; Bgl += (size_t)n0*1024;
    }

    FC acc[MF][NF];
    #pragma unroll
    for (int i=0;i<MF;i++) {
        #pragma unroll
        for (int j=0;j<NF;j++) wmma::fill_fragment(acc[i][j], 0.f);
    }

    auto issue = [&](int s, int kk){
        uint32_t st = sb + s*STAGE_BYTES;
        #pragma unroll
        for (int i=0;i<2;i++){
            int idx = t + i*256, row = idx>>2, c4 = idx&3;
            uint32_t so = (uint32_t)(row*LDSH + c4*8)*2;
            CPA(st + AHI_OFF + so, Agh + (size_t)row*LDAg + kk + c4*8);
            CPA(st + ALO_OFF + so, Agl + (size_t)row*LDAg + kk + c4*8);
        }
        #pragma unroll
        for (int i=0;i<2;i++){
            int idx = t + i*256, row = idx>>2, c4 = idx&3;
            uint32_t so = (uint32_t)(row*LDSH + c4*8)*2;
            CPA(st + BHI_OFF + so, Bgh + (size_t)row*LDBg + kk + c4*8);
            CPA(st + BLO_OFF + so, Bgl + (size_t)row*LDBg + kk + c4*8);
        }
        CPC();
    };

    auto do_mma = [&](int s){
        const __half* Ah = (const __half*)(smem + s*STAGE_BYTES + AHI_OFF);
        const __half* Al = (const __half*)(smem + s*STAGE_BYTES + ALO_OFF);
        const __half* Bh = (const __half*)(smem + s*STAGE_BYTES + BHI_OFF);
        const __half* Bl = (const __half*)(smem + s*STAGE_BYTES + BLO_OFF);
        #pragma unroll
        for (int kf=0; kf<32; kf+=16){
            FA ah[MF], al[MF]; FB bh[NF], bl[NF];
            #pragma unroll
            for (int i=0;i<MF;i++) wmma::load_matrix_sync(ah[i], Ah + (wr*TM + i*16)*LDSH + kf, LDSH);
            #pragma unroll
            for (int j=0;j<NF;j++) wmma::load_matrix_sync(bh[j], Bh + (wc*32 + j*16)*LDSH + kf, LDSH);
            #pragma unroll
            for (int i=0;i<MF;i++) {
                #pragma unroll
                for (int j=0;j<NF;j++) wmma::mma_sync(acc[i][j], ah[i], bh[j], acc[i][j]);
            }
            #pragma unroll
            for (int i=0;i<MF;i++) wmma::load_matrix_sync(al[i], Al + (wr*TM + i*16)*LDSH + kf, LDSH);
            #pragma unroll
            for (int i=0;i<MF;i++) {
                #pragma unroll
                for (int j=0;j<NF;j++) wmma::mma_sync(acc[i][j], al[i], bh[j], acc[i][j]);
            }
            #pragma unroll
            for (int j=0;j<NF;j++) wmma::load_matrix_sync(bl[j], Bl + (wc*32 + j*16)*LDSH + kf, LDSH);
            #pragma unroll
            for (int i=0;i<MF;i++) {
                #pragma unroll
                for (int j=0;j<NF;j++) wmma::mma_sync(acc[i][j], ah[i], bl[j], acc[i][j]);
            }
        }
    };

    // ---- main loop: 2-stage, single sync per iteration ----
    issue(0,0);
    for (int k=0;k<NK;k++){
        CPW0();
        __syncthreads();
        if (k+1<NK) issue((k+1)&1, (k+1)*32);
        do_mma(k&1);
    }
    __syncthreads();

    // ---- epilogue via fp32 smem staging ----
    float* Cs = (float*)smem;
    #pragma unroll
    for (int i=0;i<MF;i++) {
        #pragma unroll
        for (int j=0;j<NF;j++)
            wmma::store_matrix_sync(Cs + (wr*TM + i*16)*LDC + wc*32 + j*16, acc[i][j], LDC, wmma::mem_row_major);
    }
    __syncthreads();

    if (MODE==1) {
        int c = t & 127, rh = t >> 7;
        int n = n0 + c, h = n >> 6, d = n & 63;
        int bb = m0 >> 10, l0 = (m0 & 1023) + rh*64;
        size_t dst = ((size_t)(bb*NH + h)*DH + d)*SL + l0;
        float bval = bias[n];
        #pragma unroll
        for (int j8=0;j8<8;j8++){
            __half hv[8], lv[8];
            #pragma unroll
            for (int jj=0;jj<8;jj++){
                float v = Cs[(rh*64 + j8*8 + jj)*LDC + c] + bval;
                split1(v, hv[jj], lv[jj]);
            }
            *(uint4*)(Chi + dst + j8*8) = *(uint4*)hv;
            *(uint4*)(Clo + dst + j8*8) = *(uint4*)lv;
        }
    } else {
        #pragma unroll
        for (int i=0;i<64;i++){
            int idx = i*256 + t;
            int r = idx >> 7, c = idx & 127;
            float v = Cs[r*LDC + c];
            if (MODE==0){
                int m = m0 + r, bb = m>>10, l = m&1023;
                int n = n0 + c, h = n>>6, d = n&63;
                v += bias[n];
                __half hv,lv; split1(v,hv,lv);
                size_t dst = ((size_t)(bb*NH + h)*SL + l)*DH + d;
                Chi[dst]=hv; Clo[dst]=lv;
            } else if (MODE==2){
                Cf[(size_t)(m0+r)*ED + n0 + c] = v + bias[n0+c];
            } else {
                Cf[((size_t)bz<<20) + (size_t)(m0+r)*SL + n0 + c] = v * 0.125f;
            }
        }
    }
}

// ============================================================
// AV: O = P @ Vt^T.  z<64 pos else neg.  P fp32 read to registers,
// split to DOUBLE-buffered smem planes; V triple-buffered via
// cp.async.  2 syncs per k-iteration (was 3).
// smem: V[3]@0 (10240 ea, hi@0 lo@+2560h) | P[2]@30720 (20480 ea)
//       total 71680; epilogue fp32 (34816) overlays.
// ============================================================
#define AV_VB(s)  ((s)*10240)
#define AV_PB(s)  (30720 + (s)*20480)
#define AV_SMEM   71680

__global__ __launch_bounds__(256)
void av_gemm(const float* __restrict__ posA, const float* __restrict__ negA,
             const __half* __restrict__ Vth, const __half* __restrict__ Vtl,
             __half* __restrict__ Ohi, __half* __restrict__ Olo)
{
    extern __shared__ char smem[];
    const uint32_t sb = s2u(smem);
    const int t = threadIdx.x;
    const int wid = t >> 5;
    const int wr = wid & 3, wc = wid >> 2;      // 4x2 warps -> 128x64
    const int m0 = blockIdx.y * 128;
    const int z  = blockIdx.z;
    const int bh = z & 63;

    const float* Pg = (z < BHN ? posA : negA) + ((size_t)bh<<20) + (size_t)m0*1024;
    const __half* Vh = Vth + (size_t)bh*DH*SL;
    const __half* Vl = Vtl + (size_t)bh*DH*SL;

    FC acc[2][2];
    #pragma unroll
    for (int i=0;i<2;i++) {
        #pragma unroll
        for (int j=0;j<2;j++) wmma::fill_fragment(acc[i][j], 0.f);
    }

    auto issueV = [&](int s, int l0){
        uint32_t Vst = sb + AV_VB(s);
        int row = t>>2, c4 = t&3;
        uint32_t so = (uint32_t)(row*80 + c4*16);
        CPA(Vst + so,        Vh + (size_t)row*1024 + l0 + c4*8);
        CPA(Vst + 5120 + so, Vl + (size_t)row*1024 + l0 + c4*8);
        CPC();
    };

    float4 pr[4];
    auto loadP = [&](int kk){
        #pragma unroll
        for (int i=0;i<4;i++){
            int idx = t + i*256, row = idx>>3, c4 = idx&7;
            pr[i] = *(const float4*)(Pg + (size_t)row*1024 + kk + c4*4);
        }
    };
    auto storeP = [&](int s){
        __half* ah = (__half*)(smem + AV_PB(s));
        __half* al = ah + 5120;
        #pragma unroll
        for (int i=0;i<4;i++){
            int idx = t + i*256, row = idx>>3, c4 = idx&7;
            const float* v = &pr[i].x;
            #pragma unroll
            for (int j=0;j<4;j++){
                __half h,l; split1(v[j], h, l);
                ah[row*40 + c4*4 + j] = h;
                al[row*40 + c4*4 + j] = l;
            }
        }
    };

    issueV(0,0); issueV(1,32);
    loadP(0);
    for (int k=0;k<32;k++){
        if (k+1<32) { CPW1(); } else { CPW0(); }
        __syncthreads();                          // sync_a: V[k%3] ready; all warps done mma(k-1)
        if (k+2<32) issueV((k+2)%3, (k+2)*32);    // (k+2)%3 == (k-1)%3, but mma(k-1) done (sync_a)
        storeP(k&1);                              // plane k&1; mma(k-1) used (k-1)&1
        __syncthreads();                          // sync_b: split visible
        if (k+1<32) loadP((k+1)*32);

        const __half* Ph = (const __half*)(smem + AV_PB(k&1));
        const __half* Pl = Ph + 5120;
        const __half* Vbh = (const __half*)(smem + AV_VB(k%3));
        const __half* Vbl = Vbh + 2560;
        #pragma unroll
        for (int kf=0; kf<32; kf+=16){
            FA ah[2], al[2]; FB bh2[2], bl2[2];
            #pragma unroll
            for (int i=0;i<2;i++) wmma::load_matrix_sync(ah[i], Ph + (wr*32 + i*16)*40 + kf, 40);
            #pragma unroll
            for (int j=0;j<2;j++) wmma::load_matrix_sync(bh2[j], Vbh + (wc*32 + j*16)*40 + kf, 40);
            #pragma unroll
            for (int i=0;i<2;i++) {
                #pragma unroll
                for (int j=0;j<2;j++) wmma::mma_sync(acc[i][j], ah[i], bh2[j], acc[i][j]);
            }
            #pragma unroll
            for (int i=0;i<2;i++) wmma::load_matrix_sync(al[i], Pl + (wr*32 + i*16)*40 + kf, 40);
            #pragma unroll
            for (int i=0;i<2;i++) {
                #pragma unroll
                for (int j=0;j<2;j++) wmma::mma_sync(acc[i][j], al[i], bh2[j], acc[i][j]);
            }
            #pragma unroll
            for (int j=0;j<2;j++) wmma::load_matrix_sync(bl2[j], Vbl + (wc*32 + j*16)*40 + kf, 40);
            #pragma unroll
            for (int i=0;i<2;i++) {
                #pragma unroll
                for (int j=0;j<2;j++) wmma::mma_sync(acc[i][j], ah[i], bl2[j], acc[i][j]);
            }
        }
    }
    __syncthreads();

    // epilogue
    const int b = bh >> 4, h = bh & 15;
    float* Cs = (float*)smem;
    #pragma unroll
    for (int i=0;i<2;i++) {
        #pragma unroll
        for (int j=0;j<2;j++)
            wmma::store_matrix_sync(Cs + (wr*32 + i*16)*68 + wc*32 + j*16, acc[i][j], 68, wmma::mem_row_major);
    }
    __syncthreads();
    size_t pbase = (z < BHN ? 0 : (size_t)MTOT*ED);
    #pragma unroll
    for (int i=0;i<32;i++){
        int idx = i*256 + t;
        int r = idx >> 6, c = idx & 63;
        float v = Cs[r*68 + c];
        __half hv,lv; split1(v,hv,lv);
        size_t dst = pbase + ((size_t)b*SL + m0 + r)*ED + (size_t)h*DH + c;
        Ohi[dst]=hv; Olo[dst]=lv;
    }
}

// ============================================================
// fp32 -> fp16 hi/lo split (elementwise)
// ============================================================
__global__ void split_kernel(const float4* __restrict__ src, __half2* __restrict__ hi,
                             __half2* __restrict__ lo, int n4)
{
    int i = blockIdx.x*blockDim.x + threadIdx.x;
    if (i >= n4) return;
    float4 v = src[i];
    __half hx,lx,hy,ly,hz,lz,hw,lw;
    split1(v.x,hx,lx); split1(v.y,hy,ly); split1(v.z,hz,lz); split1(v.w,hw,lw);
    hi[2*i]   = __halves2half2(hx,hy);
    hi[2*i+1] = __halves2half2(hz,hw);
    lo[2*i]   = __halves2half2(lx,ly);
    lo[2*i+1] = __halves2half2(lz,lw);
}

// ============================================================
// Warp-per-row softmax + neg-attn. 8 warps/block, no block barriers.
// ============================================================
__global__ __launch_bounds__(256)
void softmax_neg_warp(float* __restrict__ pos, float* __restrict__ neg)
{
    const int warp = threadIdx.x >> 5, lane = threadIdx.x & 31;
    const size_t row = (size_t)blockIdx.x*8 + warp;
    float4* prow = (float4*)(pos + row*SL);
    float4* nrow = (float4*)(neg + row*SL);

    float4 v[8];
    #pragma unroll
    for (int i=0;i<8;i++) v[i] = prow[lane + 32*i];

    float m = -1e30f;
    #pragma unroll
    for (int i=0;i<8;i++) m = fmaxf(m, fmaxf(fmaxf(v[i].x,v[i].y), fmaxf(v[i].z,v[i].w)));
    #pragma unroll
    for (int o=16;o>0;o>>=1) m = fmaxf(m, __shfl_xor_sync(0xFFFFFFFFu, m, o));

    float s0 = 0.f;
    #pragma unroll
    for (int i=0;i<8;i++){
        v[i].x = expf(v[i].x - m); v[i].y = expf(v[i].y - m);
        v[i].z = expf(v[i].z - m); v[i].w = expf(v[i].w - m);
        s0 += (v[i].x + v[i].y) + (v[i].z + v[i].w);
    }
    #pragma unroll
    for (int o=16;o>0;o>>=1) s0 += __shfl_xor_sync(0xFFFFFFFFu, s0, o);
    float invS0 = 1.f / s0;

    float l1 = 0.f;
    #pragma unroll
    for (int i=0;i<8;i++){
        v[i].x *= invS0; v[i].y *= invS0; v[i].z *= invS0; v[i].w *= invS0;
        l1 += (1.f-v[i].x) + (1.f-v[i].y) + (1.f-v[i].z) + (1.f-v[i].w);
    }
    #pragma unroll
    for (int o=16;o>0;o>>=1) l1 += __shfl_xor_sync(0xFFFFFFFFu, l1, o);
    float invS1 = 1.f / l1;

    float4 tv[8];
    float l2 = 0.f;
    #pragma unroll
    for (int i=0;i<8;i++){
        tv[i].x = fminf((1.f-v[i].x)*invS1, 1e-6f/(v[i].x+1e-10f));
        tv[i].y = fminf((1.f-v[i].y)*invS1, 1e-6f/(v[i].y+1e-10f));
        tv[i].z = fminf((1.f-v[i].z)*invS1, 1e-6f/(v[i].z+1e-10f));
        tv[i].w = fminf((1.f-v[i].w)*invS1, 1e-6f/(v[i].w+1e-10f));
        l2 += (tv[i].x + tv[i].y) + (tv[i].z + tv[i].w);
    }
    #pragma unroll
    for (int o=16;o>0;o>>=1) l2 += __shfl_xor_sync(0xFFFFFFFFu, l2, o);
    float invS2 = 1.f / l2;

    #pragma unroll
    for (int i=0;i<8;i++){
        prow[lane + 32*i] = v[i];
        float4 no = {tv[i].x*invS2, tv[i].y*invS2, tv[i].z*invS2, tv[i].w*invS2};
        nrow[lane + 32*i] = no;
    }
}

// ============================================================
extern "C" void kernel_launch(void* const* d_in, const int* in_sizes, int n_in,
                              void* d_out, int out_size)
{
    const float* query = (const float*)d_in[0];
    const float* key   = (const float*)d_in[1];
    const float* value = (const float*)d_in[2];
    const float* Wq = (const float*)d_in[3];
    const float* bq = (const float*)d_in[4];
    const float* Wk = (const float*)d_in[5];
    const float* bk = (const float*)d_in[6];
    const float* Wv = (const float*)d_in[7];
    const float* bv = (const float*)d_in[8];
    const float* Wo = (const float*)d_in[9];
    const float* bo = (const float*)d_in[10];

    float* out = (float*)d_out;
    float* pos_output = out;
    float* neg_output = out + (size_t)MTOT * ED;
    float* pos_attn   = out + (size_t)2 * MTOT * ED;
    float* neg_attn   = pos_attn + (size_t)BHN * SL * SL;

    const size_t PXE = (size_t)MTOT*ED, PWW = (size_t)ED*ED;
    const size_t PQK = (size_t)BHN*SL*DH, PO = (size_t)2*MTOT*ED;

    void *p;
    cudaGetSymbolAddress(&p, s_q);  __half* qh  = (__half*)p; __half* ql  = qh  + PXE;
    cudaGetSymbolAddress(&p, s_k);  __half* kh  = (__half*)p; __half* kl  = kh  + PXE;
    cudaGetSymbolAddress(&p, s_v);  __half* vh  = (__half*)p; __half* vl  = vh  + PXE;
    cudaGetSymbolAddress(&p, s_Wq); __half* wqh = (__half*)p; __half* wql = wqh + PWW;
    cudaGetSymbolAddress(&p, s_Wk); __half* wkh = (__half*)p; __half* wkl = wkh + PWW;
    cudaGetSymbolAddress(&p, s_Wv); __half* wvh = (__half*)p; __half* wvl = wvh + PWW;
    cudaGetSymbolAddress(&p, s_Wo); __half* woh = (__half*)p; __half* wol = woh + PWW;
    cudaGetSymbolAddress(&p, s_Q);  __half* Qh  = (__half*)p; __half* Ql  = Qh  + PQK;
    cudaGetSymbolAddress(&p, s_K);  __half* Kh  = (__half*)p; __half* Kl  = Kh  + PQK;
    cudaGetSymbolAddress(&p, s_Vt); __half* Vth = (__half*)p; __half* Vtl = Vth + PQK;
    cudaGetSymbolAddress(&p, s_O);  __half* Oh  = (__half*)p; __half* Ol  = Oh  + PO;

    cudaFuncSetAttribute(gemm_f16<0>, cudaFuncAttributeMaxDynamicSharedMemorySize, SMEM_BYTES);
    cudaFuncSetAttribute(gemm_f16<1>, cudaFuncAttributeMaxDynamicSharedMemorySize, SMEM_BYTES);
    cudaFuncSetAttribute(gemm_f16<2>, cudaFuncAttributeMaxDynamicSharedMemorySize, SMEM_BYTES);
    cudaFuncSetAttribute(gemm_f16<3>, cudaFuncAttributeMaxDynamicSharedMemorySize, SMEM_BYTES);
    cudaFuncSetAttribute(av_gemm,     cudaFuncAttributeMaxDynamicSharedMemorySize, AV_SMEM);

    // 1) split inputs + weights
    split_kernel<<<MTOT*ED/1024, 256>>>((const float4*)query, (__half2*)qh, (__half2*)ql, MTOT*ED/4);
    split_kernel<<<MTOT*ED/1024, 256>>>((const float4*)key,   (__half2*)kh, (__half2*)kl, MTOT*ED/4);
    split_kernel<<<MTOT*ED/1024, 256>>>((const float4*)value, (__half2*)vh, (__half2*)vl, MTOT*ED/4);
    split_kernel<<<ED*ED/1024, 256>>>((const float4*)Wq, (__half2*)wqh, (__half2*)wql, ED*ED/4);
    split_kernel<<<ED*ED/1024, 256>>>((const float4*)Wk, (__half2*)wkh, (__half2*)wkl, ED*ED/4);
    split_kernel<<<ED*ED/1024, 256>>>((const float4*)Wv, (__half2*)wvh, (__half2*)wvl, ED*ED/4);
    split_kernel<<<ED*ED/1024, 256>>>((const float4*)Wo, (__half2*)woh, (__half2*)wol, ED*ED/4);

    // 2) projections
    dim3 pg(ED/128, MTOT/128);      // (8, 32)
    gemm_f16<0><<<pg, 256, SMEM_BYTES>>>(qh,ql, wqh,wql, bq, nullptr, Qh, Ql);
    gemm_f16<0><<<pg, 256, SMEM_BYTES>>>(kh,kl, wkh,wkl, bk, nullptr, Kh, Kl);
    gemm_f16<1><<<pg, 256, SMEM_BYTES>>>(vh,vl, wvh,wvl, bv, nullptr, Vth, Vtl);

    // 3) scores -> raw s into pos_attn
    gemm_f16<3><<<dim3(SL/128, SL/128, BHN), 256, SMEM_BYTES>>>(Qh,Ql, Kh,Kl, nullptr, pos_attn, nullptr, nullptr);

    // 4) softmax + neg (warp-per-row)
    softmax_neg_warp<<<BHN*SL/8, 256>>>(pos_attn, neg_attn);

    // 5) AV (pos z<64, neg z>=64) — 2-sync triple-V version (ONLY change)
    av_gemm<<<dim3(1, SL/128, 2*BHN), 256, AV_SMEM>>>(pos_attn, neg_attn, Vth, Vtl, Oh, Ol);

    // 6) output projections
    gemm_f16<2><<<pg, 256, SMEM_BYTES>>>(Oh,Ol,           woh,wol, bo, pos_output, nullptr, nullptr);
    gemm_f16<2><<<pg, 256, SMEM_BYTES>>>(Oh+PXE,Ol+PXE,   woh,wol, bo, neg_output, nullptr, nullptr);
}

// round 16
// speedup vs baseline: 1.0240x; 1.0240x over previous
#include <cuda_runtime.h>
#include <cuda_fp16.h>
#include <mma.h>
#include <math.h>
#include <cstdint>

using namespace nvcuda;

#define NB 4
#define NH 16
#define SL 1024
#define DH 64
#define ED 1024
#define MTOT (NB*SL)          // 4096
#define BHN (NB*NH)           // 64

// ---- fp16 hi/lo split scratch (allocation-free) ----
__device__ __half s_q [2][(size_t)MTOT*ED];
__device__ __half s_k [2][(size_t)MTOT*ED];
__device__ __half s_v [2][(size_t)MTOT*ED];
__device__ __half s_Wq[2][(size_t)ED*ED];
__device__ __half s_Wk[2][(size_t)ED*ED];
__device__ __half s_Wv[2][(size_t)ED*ED];
__device__ __half s_Wo[2][(size_t)ED*ED];
__device__ __half s_Q [2][(size_t)BHN*SL*DH];   // [bh][l][d]
__device__ __half s_K [2][(size_t)BHN*SL*DH];   // [bh][l][d]
__device__ __half s_Vt[2][(size_t)BHN*DH*SL];   // [bh][d][l]
__device__ __half s_O [2][(size_t)2*MTOT*ED];   // pos|neg [B,L,E]

#define STAGE_BYTES 40960
#define AHI_OFF 0
#define ALO_OFF 10240
#define BHI_OFF 20480
#define BLO_OFF 30720
#define SMEM_BYTES 81920
#define LDSH 40                // smem fp16 row stride (halves)
#define LDC 136                // smem fp32 epilogue stride

__device__ __forceinline__ uint32_t s2u(const void* p){
    uint32_t a; asm("{ .reg .u64 t; cvta.to.shared.u64 t, %1; cvt.u32.u64 %0, t; }":"=r"(a):"l"(p)); return a;
}
#define CPA(dst, src) asm volatile("cp.async.cg.shared.global [%0], [%1], 16;" :: "r"(dst), "l"(src))
#define CPC()  asm volatile("cp.async.commit_group;")
#define CPW0() asm volatile("cp.async.wait_group 0;")
#define CPW1() asm volatile("cp.async.wait_group 1;")

__device__ __forceinline__ void split1(float x, __half& h, __half& l){
    h = __float2half_rn(x);
    l = __float2half_rn(x - __half2float(h));
}

typedef wmma::fragment<wmma::matrix_a, 16,16,16, __half, wmma::row_major> FA;
typedef wmma::fragment<wmma::matrix_b, 16,16,16, __half, wmma::col_major> FB;
typedef wmma::fragment<wmma::accumulator, 16,16,16, float> FC;

// ============================================================
// MODE 0: C=A@W^T+bias -> fp16 hi/lo scatter [bh][l][d]   (Q/K proj)
// MODE 1: C=A@W^T+bias -> fp16 hi/lo scatter [bh][d][l]   (V proj -> Vt)
// MODE 2: C=A@W^T+bias -> fp32 [m][n]                     (out proj)
// MODE 3: S = Q@K^T * 0.125 -> fp32  (per-head, Kdim=64)
// MODE 4: O = P@Vt^T -> fp16 hi/lo planes (P fp32, split in-kernel;
//         P uses HI plane only — prob values, 2^-12 rel is enough)
// ============================================================
template<int MODE>
__global__ __launch_bounds__(256)
void gemm_f16(const __half* __restrict__ Agh, const __half* __restrict__ Agl,
              const __half* __restrict__ Bgh, const __half* __restrict__ Bgl,
              const float* __restrict__ bias, const float* __restrict__ Pf,
              float* __restrict__ Cf, __half* __restrict__ Chi, __half* __restrict__ Clo)
{
    constexpr int BN   = (MODE==4) ? 64 : 128;
    constexpr int NK   = (MODE==3) ? 2  : 32;
    constexpr int LDAg = (MODE==3) ? 64 : 1024;
    constexpr int LDBg = (MODE==3) ? 64 : 1024;
    constexpr int WROWS= (MODE==4) ? 4 : 2;
    constexpr int TM   = 128/WROWS;            // 32 or 64
    constexpr int MF   = TM/16;                // 2 or 4
    constexpr int NF   = 2;                    // warp n-tile always 32

    extern __shared__ char smem[];
    const uint32_t sb = s2u(smem);
    const int t = threadIdx.x;
    const int wid = t >> 5;
    const int wr = wid % WROWS, wc = wid / WROWS;

    const int m0 = blockIdx.y * 128;
    const int n0 = (MODE==4) ? 0 : blockIdx.x * BN;
    const int bz = blockIdx.z;

    const float* Pg = nullptr;
    if (MODE==3) {
        size_t ab = ((size_t)bz*SL + m0) * 64, bb = ((size_t)bz*SL + n0) * 64;
        Agh += ab; Agl += ab; Bgh += bb; Bgl += bb;
    } else if (MODE==4) {
        Pg = Pf + ((size_t)bz<<20) + (size_t)m0*1024;
        size_t bb = (size_t)(bz & 63) * DH * SL;
        Bgh += bb; Bgl += bb;
    } else {
        Agh += (size_t)m0*1024; Agl += (size_t)m0*1024;
        Bgh += (size_t)n0*1024; Bgl += (size_t)n0*1024;
    }

    FC acc[MF][NF];
    #pragma unroll
    for (int i=0;i<MF;i++) {
        #pragma unroll
        for (int j=0;j<NF;j++) wmma::fill_fragment(acc[i][j], 0.f);
    }

    // ---- loaders ----
    auto issue = [&](int s, int kk){
        uint32_t st = sb + s*STAGE_BYTES;
        if (MODE != 4) {
            #pragma unroll
            for (int i=0;i<2;i++){
                int idx = t + i*256, row = idx>>2, c4 = idx&3;
                uint32_t so = (uint32_t)(row*LDSH + c4*8)*2;
                CPA(st + AHI_OFF + so, Agh + (size_t)row*LDAg + kk + c4*8);
                CPA(st + ALO_OFF + so, Agl + (size_t)row*LDAg + kk + c4*8);
            }
        }
        constexpr int BI = (BN==128) ? 2 : 1;
        #pragma unroll
        for (int i=0;i<BI;i++){
            int idx = t + i*256, row = idx>>2, c4 = idx&3;
            uint32_t so = (uint32_t)(row*LDSH + c4*8)*2;
            CPA(st + BHI_OFF + so, Bgh + (size_t)row*LDBg + kk + c4*8);
            CPA(st + BLO_OFF + so, Bgl + (size_t)row*LDBg + kk + c4*8);
        }
        CPC();
    };

    float4 pr[4];
    auto loadP = [&](int kk){
        #pragma unroll
        for (int i=0;i<4;i++){
            int idx = t + i*256, row = idx>>3, c4 = idx&7;
            pr[i] = *(const float4*)(Pg + (size_t)row*1024 + kk + c4*4);
        }
    };
    auto storeP = [&](){
        __half* ah = (__half*)(smem + AHI_OFF);
        #pragma unroll
        for (int i=0;i<4;i++){
            int idx = t + i*256, row = idx>>3, c4 = idx&7;
            const float* v = &pr[i].x;
            __half hv[4];
            #pragma unroll
            for (int j=0;j<4;j++) hv[j] = __float2half_rn(v[j]);
            *(uint2*)(ah + row*LDSH + c4*4) = *(uint2*)hv;
        }
    };

    auto do_mma = [&](int s){
        const __half* Ah = (const __half*)(smem + (MODE==4 ? 0 : s*STAGE_BYTES) + AHI_OFF);
        const __half* Al = (const __half*)(smem + (MODE==4 ? 0 : s*STAGE_BYTES) + ALO_OFF);
        const __half* Bh = (const __half*)(smem + s*STAGE_BYTES + BHI_OFF);
        const __half* Bl = (const __half*)(smem + s*STAGE_BYTES + BLO_OFF);
        #pragma unroll
        for (int kf=0; kf<32; kf+=16){
            FA ah[MF], al[MF]; FB bh[NF], bl[NF];
            #pragma unroll
            for (int i=0;i<MF;i++) wmma::load_matrix_sync(ah[i], Ah + (wr*TM + i*16)*LDSH + kf, LDSH);
            #pragma unroll
            for (int j=0;j<NF;j++) wmma::load_matrix_sync(bh[j], Bh + (wc*32 + j*16)*LDSH + kf, LDSH);
            #pragma unroll
            for (int i=0;i<MF;i++) {
                #pragma unroll
                for (int j=0;j<NF;j++) wmma::mma_sync(acc[i][j], ah[i], bh[j], acc[i][j]);
            }
            if (MODE != 4) {
                #pragma unroll
                for (int i=0;i<MF;i++) wmma::load_matrix_sync(al[i], Al + (wr*TM + i*16)*LDSH + kf, LDSH);
                #pragma unroll
                for (int i=0;i<MF;i++) {
                    #pragma unroll
                    for (int j=0;j<NF;j++) wmma::mma_sync(acc[i][j], al[i], bh[j], acc[i][j]);
                }
            }
            #pragma unroll
            for (int j=0;j<NF;j++) wmma::load_matrix_sync(bl[j], Bl + (wc*32 + j*16)*LDSH + kf, LDSH);
            #pragma unroll
            for (int i=0;i<MF;i++) {
                #pragma unroll
                for (int j=0;j<NF;j++) wmma::mma_sync(acc[i][j], ah[i], bl[j], acc[i][j]);
            }
        }
    };

    // ---- main loop ----
    issue(0,0);
    if (MODE==4) {
        loadP(0);
        for (int k=0;k<NK;k++){
            if (k+1<NK) { issue((k+1)&1, (k+1)*32); CPW1(); } else { CPW0(); }
            __syncthreads();
            storeP();
            __syncthreads();
            if (k+1<NK) loadP((k+1)*32);
            do_mma(k&1);
            __syncthreads();
        }
    } else {
        // single sync per iteration (prefetch after barrier; WAR safe:
        // buffer being written was last read before the previous barrier)
        for (int k=0;k<NK;k++){
            CPW0();
            __syncthreads();
            if (k+1<NK) issue((k+1)&1, (k+1)*32);
            do_mma(k&1);
        }
        __syncthreads();
    }

    // ---- epilogue via fp32 smem staging ----
    float* Cs = (float*)smem;
    #pragma unroll
    for (int i=0;i<MF;i++) {
        #pragma unroll
        for (int j=0;j<NF;j++)
            wmma::store_matrix_sync(Cs + (wr*TM + i*16)*LDC + wc*32 + j*16, acc[i][j], LDC, wmma::mem_row_major);
    }
    __syncthreads();

    if (MODE==1) {
        int c = t & 127, rh = t >> 7;                 // rh in 0..1
        int n = n0 + c, h = n >> 6, d = n & 63;
        int bb = m0 >> 10, l0 = (m0 & 1023) + rh*64;
        size_t dst = ((size_t)(bb*NH + h)*DH + d)*SL + l0;
        float bval = bias[n];
        #pragma unroll
        for (int j8=0;j8<8;j8++){
            __half hv[8], lv[8];
            #pragma unroll
            for (int jj=0;jj<8;jj++){
                float v = Cs[(rh*64 + j8*8 + jj)*LDC + c] + bval;
                split1(v, hv[jj], lv[jj]);
            }
            *(uint4*)(Chi + dst + j8*8) = *(uint4*)hv;
            *(uint4*)(Clo + dst + j8*8) = *(uint4*)lv;
        }
    } else {
        constexpr int PER = 128*BN/256;
        #pragma unroll
        for (int i=0;i<PER;i++){
            int idx = i*256 + t;
            int r = idx / BN, c = idx % BN;
            float v = Cs[r*LDC + c];
            if (MODE==0){
                int m = m0 + r, bb = m>>10, l = m&1023;
                int n = n0 + c, h = n>>6, d = n&63;
                v += bias[n];
                __half hv,lv; split1(v,hv,lv);
                size_t dst = ((size_t)(bb*NH + h)*SL + l)*DH + d;
                Chi[dst]=hv; Clo[dst]=lv;
            } else if (MODE==2){
                Cf[(size_t)(m0+r)*ED + n0 + c] = v + bias[n0+c];
            } else if (MODE==3){
                Cf[((size_t)bz<<20) + (size_t)(m0+r)*SL + n0 + c] = v * 0.125f;
            } else { // MODE 4
                int bh = bz & 63, bb = bh>>4, h = bh&15;
                int l = m0 + r;
                __half hv,lv; split1(v,hv,lv);
                size_t dst = ((bz<BHN)?0:(size_t)MTOT*ED) + ((size_t)bb*SL + l)*ED + (size_t)h*DH + c;
                Chi[dst]=hv; Clo[dst]=lv;
            }
        }
    }
}

// ============================================================
// fp32 -> fp16 hi/lo split (elementwise)
// ============================================================
__global__ void split_kernel(const float4* __restrict__ src, __half2* __restrict__ hi,
                             __half2* __restrict__ lo, int n4)
{
    int i = blockIdx.x*blockDim.x + threadIdx.x;
    if (i >= n4) return;
    float4 v = src[i];
    __half hx,lx,hy,ly,hz,lz,hw,lw;
    split1(v.x,hx,lx); split1(v.y,hy,ly); split1(v.z,hz,lz); split1(v.w,hw,lw);
    hi[2*i]   = __halves2half2(hx,hy);
    hi[2*i+1] = __halves2half2(hz,hw);
    lo[2*i]   = __halves2half2(lx,ly);
    lo[2*i+1] = __halves2half2(lz,lw);
}

// ============================================================
// Warp-per-row softmax + neg-attn. 8 warps/block, no block barriers.
// ============================================================
__global__ __launch_bounds__(256)
void softmax_neg_warp(float* __restrict__ pos, float* __restrict__ neg)
{
    const int warp = threadIdx.x >> 5, lane = threadIdx.x & 31;
    const size_t row = (size_t)blockIdx.x*8 + warp;
    float4* prow = (float4*)(pos + row*SL);
    float4* nrow = (float4*)(neg + row*SL);

    float4 v[8];
    #pragma unroll
    for (int i=0;i<8;i++) v[i] = prow[lane + 32*i];

    float m = -1e30f;
    #pragma unroll
    for (int i=0;i<8;i++) m = fmaxf(m, fmaxf(fmaxf(v[i].x,v[i].y), fmaxf(v[i].z,v[i].w)));
    #pragma unroll
    for (int o=16;o>0;o>>=1) m = fmaxf(m, __shfl_xor_sync(0xFFFFFFFFu, m, o));

    float s0 = 0.f;
    #pragma unroll
    for (int i=0;i<8;i++){
        v[i].x = expf(v[i].x - m); v[i].y = expf(v[i].y - m);
        v[i].z = expf(v[i].z - m); v[i].w = expf(v[i].w - m);
        s0 += (v[i].x + v[i].y) + (v[i].z + v[i].w);
    }
    #pragma unroll
    for (int o=16;o>0;o>>=1) s0 += __shfl_xor_sync(0xFFFFFFFFu, s0, o);
    float invS0 = 1.f / s0;

    float l1 = 0.f;
    #pragma unroll
    for (int i=0;i<8;i++){
        v[i].x *= invS0; v[i].y *= invS0; v[i].z *= invS0; v[i].w *= invS0;
        l1 += (1.f-v[i].x) + (1.f-v[i].y) + (1.f-v[i].z) + (1.f-v[i].w);
    }
    #pragma unroll
    for (int o=16;o>0;o>>=1) l1 += __shfl_xor_sync(0xFFFFFFFFu, l1, o);
    float invS1 = 1.f / l1;

    float4 tv[8];
    float l2 = 0.f;
    #pragma unroll
    for (int i=0;i<8;i++){
        tv[i].x = fminf((1.f-v[i].x)*invS1, 1e-6f/(v[i].x+1e-10f));
        tv[i].y = fminf((1.f-v[i].y)*invS1, 1e-6f/(v[i].y+1e-10f));
        tv[i].z = fminf((1.f-v[i].z)*invS1, 1e-6f/(v[i].z+1e-10f));
        tv[i].w = fminf((1.f-v[i].w)*invS1, 1e-6f/(v[i].w+1e-10f));
        l2 += (tv[i].x + tv[i].y) + (tv[i].z + tv[i].w);
    }
    #pragma unroll
    for (int o=16;o>0;o>>=1) l2 += __shfl_xor_sync(0xFFFFFFFFu, l2, o);
    float invS2 = 1.f / l2;

    #pragma unroll
    for (int i=0;i<8;i++){
        prow[lane + 32*i] = v[i];
        float4 no = {tv[i].x*invS2, tv[i].y*invS2, tv[i].z*invS2, tv[i].w*invS2};
        nrow[lane + 32*i] = no;
    }
}

// ============================================================
extern "C" void kernel_launch(void* const* d_in, const int* in_sizes, int n_in,
                              void* d_out, int out_size)
{
    const float* query = (const float*)d_in[0];
    const float* key   = (const float*)d_in[1];
    const float* value = (const float*)d_in[2];
    const float* Wq = (const float*)d_in[3];
    const float* bq = (const float*)d_in[4];
    const float* Wk = (const float*)d_in[5];
    const float* bk = (const float*)d_in[6];
    const float* Wv = (const float*)d_in[7];
    const float* bv = (const float*)d_in[8];
    const float* Wo = (const float*)d_in[9];
    const float* bo = (const float*)d_in[10];

    float* out = (float*)d_out;
    float* pos_output = out;
    float* neg_output = out + (size_t)MTOT * ED;
    float* pos_attn   = out + (size_t)2 * MTOT * ED;
    float* neg_attn   = pos_attn + (size_t)BHN * SL * SL;

    const size_t PXE = (size_t)MTOT*ED, PWW = (size_t)ED*ED;
    const size_t PQK = (size_t)BHN*SL*DH, PO = (size_t)2*MTOT*ED;

    void *p;
    cudaGetSymbolAddress(&p, s_q);  __half* qh  = (__half*)p; __half* ql  = qh  + PXE;
    cudaGetSymbolAddress(&p, s_k);  __half* kh  = (__half*)p; __half* kl  = kh  + PXE;
    cudaGetSymbolAddress(&p, s_v);  __half* vh  = (__half*)p; __half* vl  = vh  + PXE;
    cudaGetSymbolAddress(&p, s_Wq); __half* wqh = (__half*)p; __half* wql = wqh + PWW;
    cudaGetSymbolAddress(&p, s_Wk); __half* wkh = (__half*)p; __half* wkl = wkh + PWW;
    cudaGetSymbolAddress(&p, s_Wv); __half* wvh = (__half*)p; __half* wvl = wvh + PWW;
    cudaGetSymbolAddress(&p, s_Wo); __half* woh = (__half*)p; __half* wol = woh + PWW;
    cudaGetSymbolAddress(&p, s_Q);  __half* Qh  = (__half*)p; __half* Ql  = Qh  + PQK;
    cudaGetSymbolAddress(&p, s_K);  __half* Kh  = (__half*)p; __half* Kl  = Kh  + PQK;
    cudaGetSymbolAddress(&p, s_Vt); __half* Vth = (__half*)p; __half* Vtl = Vth + PQK;
    cudaGetSymbolAddress(&p, s_O);  __half* Oh  = (__half*)p; __half* Ol  = Oh  + PO;

    cudaFuncSetAttribute(gemm_f16<0>, cudaFuncAttributeMaxDynamicSharedMemorySize, SMEM_BYTES);
    cudaFuncSetAttribute(gemm_f16<1>, cudaFuncAttributeMaxDynamicSharedMemorySize, SMEM_BYTES);
    cudaFuncSetAttribute(gemm_f16<2>, cudaFuncAttributeMaxDynamicSharedMemorySize, SMEM_BYTES);
    cudaFuncSetAttribute(gemm_f16<3>, cudaFuncAttributeMaxDynamicSharedMemorySize, SMEM_BYTES);
    cudaFuncSetAttribute(gemm_f16<4>, cudaFuncAttributeMaxDynamicSharedMemorySize, SMEM_BYTES);

    // 1) split inputs + weights
    split_kernel<<<MTOT*ED/1024, 256>>>((const float4*)query, (__half2*)qh, (__half2*)ql, MTOT*ED/4);
    split_kernel<<<MTOT*ED/1024, 256>>>((const float4*)key,   (__half2*)kh, (__half2*)kl, MTOT*ED/4);
    split_kernel<<<MTOT*ED/1024, 256>>>((const float4*)value, (__half2*)vh, (__half2*)vl, MTOT*ED/4);
    split_kernel<<<ED*ED/1024, 256>>>((const float4*)Wq, (__half2*)wqh, (__half2*)wql, ED*ED/4);
    split_kernel<<<ED*ED/1024, 256>>>((const float4*)Wk, (__half2*)wkh, (__half2*)wkl, ED*ED/4);
    split_kernel<<<ED*ED/1024, 256>>>((const float4*)Wv, (__half2*)wvh, (__half2*)wvl, ED*ED/4);
    split_kernel<<<ED*ED/1024, 256>>>((const float4*)Wo, (__half2*)woh, (__half2*)wol, ED*ED/4);

    // 2) projections
    dim3 pg(ED/128, MTOT/128);      // (8, 32)
    gemm_f16<0><<<pg, 256, SMEM_BYTES>>>(qh,ql, wqh,wql, bq, nullptr, nullptr, Qh, Ql);
    gemm_f16<0><<<pg, 256, SMEM_BYTES>>>(kh,kl, wkh,wkl, bk, nullptr, nullptr, Kh, Kl);
    gemm_f16<1><<<pg, 256, SMEM_BYTES>>>(vh,vl, wvh,wvl, bv, nullptr, nullptr, Vth, Vtl);

    // 3) scores -> raw s into pos_attn
    gemm_f16<3><<<dim3(SL/128, SL/128, BHN), 256, SMEM_BYTES>>>(Qh,Ql, Kh,Kl, nullptr, nullptr, pos_attn, nullptr, nullptr);

    // 4) softmax + neg (warp-per-row)
    softmax_neg_warp<<<BHN*SL/8, 256>>>(pos_attn, neg_attn);

    // 5) AV (pos z<64, neg z>=64), P hi-only (ONLY change vs best kernel)
    gemm_f16<4><<<dim3(1, SL/128, 2*BHN), 256, SMEM_BYTES>>>(nullptr,nullptr, Vth,Vtl, nullptr, pos_attn, nullptr, Oh, Ol);

    // 6) output projections
    gemm_f16<2><<<pg, 256, SMEM_BYTES>>>(Oh,Ol,           woh,wol, bo, nullptr, pos_output, nullptr, nullptr);
    gemm_f16<2><<<pg, 256, SMEM_BYTES>>>(Oh+PXE,Ol+PXE,   woh,wol, bo, nullptr, neg_output, nullptr, nullptr);
}